// round 9
// baseline (speedup 1.0000x reference)
#include <cuda_runtime.h>
#include <cuda_bf16.h>
#include <cstdint>
#include <math.h>

// CharDecoder: 8192 independent LSTM decode sequences, H=512, A=128, C=20 steps.
// Row-partitioned persistent-per-CTA design; h (ping-pong) and c in SMEM.
// Numerics engineered to match XLA-GPU fp32 semantics bit-for-bit:
//  - GEMMs: single fp32 accumulator, strictly ascending-k FFMA chain, acc=0 init,
//    bias added in the epilogue (cublas/cutlass SIMT sgemm rounding order)
//  - gates = (dot_x + dot_h) + (b_ih+b_hh)   (HLO add order)
//  - tanh: XLA rational polynomial; sigmoid: 0.5*tanh(0.5x)+0.5 (logistic expander)
//  - one-hot @ w_ih.T == exact gather of w_ih columns

#define Hdim   512
#define Qdim   256
#define Adim   128
#define Csteps 20
#define Rrows  28
#define NTHR   256
#define KT     16
#define WSTR   20          // Ws stride in floats (conflict-free for LDS.128 phases)
#define NROWS  8192
#define NCTAS  293         // ceil(8192/28)

__device__ float g_wihT[Adim * 4 * Hdim];

__global__ void transpose_wih_kernel(const float* __restrict__ w_ih) {
    int id = blockIdx.x * 256 + threadIdx.x;
    if (id < Adim * 4 * Hdim) {
        int a = id >> 11;        // / 2048
        int n = id & 2047;
        g_wihT[id] = w_ih[n * Adim + a];   // one-hot @ w_ih.T selects exactly
    }
}

// XLA f32 tanh: rational polynomial, FMA Horner, clamp, tiny-x passthrough.
__device__ __forceinline__ float tanh_xla(float x) {
    float ax = fabsf(x);
    if (ax < 4e-4f) return x;
    float xc = fminf(fmaxf(x, -7.90531110763549805f), 7.90531110763549805f);
    float x2 = __fmul_rn(xc, xc);
    float p = fmaf(x2, -2.76076847742355e-16f, 2.00018790482477e-13f);
    p = fmaf(x2, p, -8.60467152213735e-11f);
    p = fmaf(x2, p,  5.12229709037114e-08f);
    p = fmaf(x2, p,  1.48572235717979e-05f);
    p = fmaf(x2, p,  6.37261928875436e-04f);
    p = fmaf(x2, p,  4.89352455891786e-03f);
    p = __fmul_rn(xc, p);
    float q = fmaf(x2, 1.19825839466702e-06f, 1.18534705686654e-04f);
    q = fmaf(x2, q, 2.26843463243900e-03f);
    q = fmaf(x2, q, 4.89352518554385e-03f);
    return __fdiv_rn(p, q);
}

// XLA logistic expansion: 0.5*tanh(0.5*x) + 0.5 (separate mul/add, no FMA).
__device__ __forceinline__ float sigmoid_xla(float x) {
    float th = tanh_xla(__fmul_rn(0.5f, x));
    return __fadd_rn(__fmul_rn(0.5f, th), 0.5f);
}

// Tiled GEMM fragment: acc[7][M] += act[7 rows] x W^T (COLS = 64*M columns).
// Weights staged cooperatively into Ws each KT-slice of K.
// SINGLE accumulator chain, strictly ascending k (cublas sgemm rounding order).
template<int M, int KTOT, bool GATES>
__device__ __forceinline__ void gemm_tile(
    float (&acc)[7][M],
    const float* __restrict__ gW, int gStride, int jc,
    const float* __restrict__ act, int actStride,
    float* __restrict__ Ws, int t, int ig, int j)
{
    const int COLS = M * 64;
    for (int k0 = 0; k0 < KTOT; k0 += KT) {
        __syncthreads();   // protect Ws from previous consumers
        const int tasks = COLS * (KT / 4);
        for (int id = t; id < tasks; id += NTHR) {
            int c = id >> 2;
            int s = id & 3;
            int n = GATES ? ((c >> 7) * Hdim + jc * 128 + (c & 127)) : c;
            float4 v = *(const float4*)(gW + (long)n * gStride + k0 + s * 4);
            *(float4*)(Ws + c * WSTR + s * 4) = v;
        }
        __syncthreads();

        #pragma unroll
        for (int kk = 0; kk < KT; kk += 4) {
            float4 av[7];
            #pragma unroll
            for (int rr = 0; rr < 7; rr++)
                av[rr] = *(const float4*)(act + (ig * 7 + rr) * actStride + k0 + kk);
            #pragma unroll
            for (int m = 0; m < M; m++) {
                float4 wv = *(const float4*)(Ws + (j + 64 * m) * WSTR + kk);
                #pragma unroll
                for (int rr = 0; rr < 7; rr++) {
                    // strictly ascending k within the single chain
                    acc[rr][m] = fmaf(av[rr].x, wv.x, acc[rr][m]);
                    acc[rr][m] = fmaf(av[rr].y, wv.y, acc[rr][m]);
                    acc[rr][m] = fmaf(av[rr].z, wv.z, acc[rr][m]);
                    acc[rr][m] = fmaf(av[rr].w, wv.w, acc[rr][m]);
                }
            }
        }
    }
}

__global__ __launch_bounds__(NTHR, 1)
void chardecoder_kernel(
    const float* __restrict__ qr,     // [8192,256]
    const float* __restrict__ w_in,   // [512,256]
    const float* __restrict__ b_in,   // [512]
    const float* __restrict__ w_hh,   // [2048,512]
    const float* __restrict__ b_ih,   // [2048]
    const float* __restrict__ b_hh,   // [2048]
    const float* __restrict__ w_out,  // [128,512]
    const float* __restrict__ b_out,  // [128]
    float* __restrict__ out)          // [8192,20,128]
{
    extern __shared__ float sm[];
    float* hA    = sm;                        // 28*512
    float* hB    = hA + Rrows * Hdim;         // 28*512
    float* cS    = hB + Rrows * Hdim;         // 28*512
    float* Ws    = cS + Rrows * Hdim;         // 512*WSTR
    float* biasS = Ws + 512 * WSTR;           // 2048
    float* boutS = biasS + 4 * Hdim;          // 128
    int*   idxS  = (int*)(boutS + Adim);      // 32
    float* logitsS = Ws;                      // reuse Ws after logits GEMM done

    const int t = threadIdx.x;
    const int rowBase = blockIdx.x * Rrows;
    const int ig = t >> 6;       // 0..3 (each covers 7 rows)
    const int j  = t & 63;       // column lane (cols j + 64*m)
    const int warp = t >> 5, lane = t & 31;

    // ---- prologue: biases, initial idx, qr tile ----
    for (int n = t; n < 4 * Hdim; n += NTHR) biasS[n] = __fadd_rn(b_ih[n], b_hh[n]);
    if (t < Adim) boutS[t] = b_out[t];
    for (int r = t; r < 32; r += NTHR) idxS[r] = 0;

    for (int x = t; x < Rrows * Qdim; x += NTHR) {
        int r = x >> 8;
        int k = x & 255;
        int rg = min(rowBase + r, NROWS - 1);
        hB[r * Qdim + k] = qr[(long)rg * Qdim + k];
    }
    __syncthreads();

    // ---- h0 = qr @ w_in.T + b_in ; c0 = 0  (chain from 0, bias last) ----
    {
        float acc[7][8];
        #pragma unroll
        for (int m = 0; m < 8; m++)
            #pragma unroll
            for (int rr = 0; rr < 7; rr++) acc[rr][m] = 0.0f;
        gemm_tile<8, Qdim, false>(acc, w_in, Qdim, 0, hB, Qdim, Ws, t, ig, j);
        #pragma unroll
        for (int m = 0; m < 8; m++) {
            int n = j + 64 * m;
            float bv = b_in[n];
            #pragma unroll
            for (int rr = 0; rr < 7; rr++) {
                int r = ig * 7 + rr;
                hA[r * Hdim + n] = __fadd_rn(acc[rr][m], bv);
                cS[r * Hdim + n] = 0.0f;
            }
        }
    }
    __syncthreads();

    float* hOld = hA;
    float* hNew = hB;

    for (int step = 0; step < Csteps; step++) {
        // ---- gates = (x@w_ih.T + h@w_hh.T) + bias ; update c, hNew ----
        for (int jc = 0; jc < 4; jc++) {
            float acc[7][8];
            #pragma unroll
            for (int m = 0; m < 8; m++)
                #pragma unroll
                for (int rr = 0; rr < 7; rr++) acc[rr][m] = 0.0f;
            gemm_tile<8, Hdim, true>(acc, w_hh, Hdim, jc, hOld, Hdim, Ws, t, ig, j);
            // epilogue: (xw + hw) + bias, activations, state update
            #pragma unroll
            for (int rr = 0; rr < 7; rr++) {
                int r = ig * 7 + rr;
                int xidx = idxS[r];
                float gate[8];
                #pragma unroll
                for (int m = 0; m < 8; m++) {
                    int g = m >> 1;
                    int jl = j + (m & 1) * 64;
                    int n = g * Hdim + jc * 128 + jl;
                    float xw = g_wihT[xidx * (4 * Hdim) + n];
                    gate[m] = __fadd_rn(__fadd_rn(xw, acc[rr][m]), biasS[n]);
                }
                #pragma unroll
                for (int s = 0; s < 2; s++) {
                    int jj = jc * 128 + j + s * 64;
                    float ii = sigmoid_xla(gate[0 + s]);
                    float ff = sigmoid_xla(gate[2 + s]);
                    float gg = tanh_xla(gate[4 + s]);
                    float oo = sigmoid_xla(gate[6 + s]);
                    float cold = cS[r * Hdim + jj];
                    float cc = __fadd_rn(__fmul_rn(ff, cold), __fmul_rn(ii, gg));
                    cS[r * Hdim + jj] = cc;
                    hNew[r * Hdim + jj] = __fmul_rn(oo, tanh_xla(cc));
                }
            }
        }
        __syncthreads();   // hNew complete

        // ---- logits = hNew @ w_out.T + b_out  (chain from 0, bias last) ----
        {
            float acc[7][2];
            #pragma unroll
            for (int m = 0; m < 2; m++)
                #pragma unroll
                for (int rr = 0; rr < 7; rr++) acc[rr][m] = 0.0f;
            gemm_tile<2, Hdim, false>(acc, w_out, Hdim, 0, hNew, Hdim, Ws, t, ig, j);
            __syncthreads();   // Ws now free -> reuse as logits buffer
            #pragma unroll
            for (int rr = 0; rr < 7; rr++) {
                int r = ig * 7 + rr;
                int rg = min(rowBase + r, NROWS - 1);
                #pragma unroll
                for (int m = 0; m < 2; m++) {
                    int a = j + 64 * m;
                    float v = __fadd_rn(acc[rr][m], boutS[a]);
                    logitsS[r * Adim + a] = v;
                    out[((long)rg * Csteps + step) * Adim + a] = v;
                }
            }
        }
        __syncthreads();

        // ---- argmax per row (first-max semantics like jnp.argmax) ----
        for (int r = warp; r < Rrows; r += 8) {
            float best = -INFINITY; int bi = 0;
            #pragma unroll
            for (int q = 0; q < 4; q++) {
                int a = lane + 32 * q;     // ascending per lane
                float v = logitsS[r * Adim + a];
                if (v > best) { best = v; bi = a; }
            }
            #pragma unroll
            for (int off = 16; off; off >>= 1) {
                float ov = __shfl_down_sync(0xffffffff, best, off);
                int   oi = __shfl_down_sync(0xffffffff, bi, off);
                if (ov > best || (ov == best && oi < bi)) { best = ov; bi = oi; }
            }
            if (lane == 0) idxS[r] = bi;
        }
        __syncthreads();

        // ping-pong h
        float* tmp = hOld; hOld = hNew; hNew = tmp;
    }
}

extern "C" void kernel_launch(void* const* d_in, const int* in_sizes, int n_in,
                              void* d_out, int out_size) {
    const float* qr    = (const float*)d_in[0];
    const float* w_in  = (const float*)d_in[1];
    const float* b_in  = (const float*)d_in[2];
    const float* w_ih  = (const float*)d_in[3];
    const float* w_hh  = (const float*)d_in[4];
    const float* b_ih  = (const float*)d_in[5];
    const float* b_hh  = (const float*)d_in[6];
    const float* w_out = (const float*)d_in[7];
    const float* b_out = (const float*)d_in[8];
    float* out = (float*)d_out;

    transpose_wih_kernel<<<(Adim * 4 * Hdim + 255) / 256, 256>>>(w_ih);

    const int smemBytes = (3 * Rrows * Hdim + 512 * WSTR + 4 * Hdim + Adim + 32) * 4;
    cudaFuncSetAttribute(chardecoder_kernel,
                         cudaFuncAttributeMaxDynamicSharedMemorySize, smemBytes);
    chardecoder_kernel<<<NCTAS, NTHR, smemBytes>>>(
        qr, w_in, b_in, w_hh, b_ih, b_hh, w_out, b_out, out);
}